// round 8
// baseline (speedup 1.0000x reference)
#include <cuda_runtime.h>

// Problem constants (fixed shapes from reference)
#define NN   100000
#define NE   1600000
#define FIN  128
#define HID  64
#define NG   64
#define NC   16

static __device__ __forceinline__ int clampi(int v, int lo, int hi) {
    return min(max(v, lo), hi);
}

// ---------------------------------------------------------------------------
// Scratch (static device globals; no runtime allocation allowed)
// ---------------------------------------------------------------------------
__device__ int   g_indeg[NN];
__device__ int   g_start[NN];
__device__ int   g_cursor[NN];
__device__ int   g_total;
__device__ float g_dis[NN];
__device__ float g_dis2[NN];
__device__ __align__(16) int   g_csrc[NE];   // CSR-by-dst: source node per slot
__device__ __align__(16) float g_cnorm[NE];  // CSR-by-dst: edge norm per slot
__device__ __align__(16) float g_h[(size_t)NN * HID];    // linear output (pre-agg)
__device__ __align__(16) float g_out[(size_t)NN * HID];  // aggregated (pre-relu)
__device__ float g_pool[NG * HID];
__device__ float g_cnt[NG];

// ---------------------------------------------------------------------------
// CSR build: count -> offsets (warp scan + one int atomic per warp) -> place
// (int atomics only; indices clamped so atomics can never leave the arrays)
// ---------------------------------------------------------------------------
__global__ void k_init(int n) {
    int i = blockIdx.x * blockDim.x + threadIdx.x;
    if (i < n) g_indeg[i] = 0;
    if (i == 0) g_total = 0;
}

__global__ void k_count(const int* __restrict__ ei, int E) {
    int e = blockIdx.x * blockDim.x + threadIdx.x;
    if (e < E) {
        int d = clampi(ei[E + e], 0, NN - 1);
        atomicAdd(&g_indeg[d], 1);
    }
}

__global__ void k_offsets(int n) {
    int i = blockIdx.x * blockDim.x + threadIdx.x;
    int lane = threadIdx.x & 31;
    int c = (i < n) ? g_indeg[i] : 0;
    // warp inclusive scan
    int v = c;
#pragma unroll
    for (int o = 1; o < 32; o <<= 1) {
        int u = __shfl_up_sync(0xFFFFFFFFu, v, o);
        if (lane >= o) v += u;
    }
    int base = 0;
    if (lane == 31) base = atomicAdd(&g_total, v);
    base = __shfl_sync(0xFFFFFFFFu, base, 31);
    if (i < n) {
        int st = base + v - c;
        g_start[i]  = st;
        g_cursor[i] = st;
        float deg = (float)c + 1.0f;   // + self-loop
        g_dis[i]  = rsqrtf(deg);
        g_dis2[i] = 1.0f / deg;
    }
}

__global__ void k_place(const int* __restrict__ ei, int E) {
    int e = blockIdx.x * blockDim.x + threadIdx.x;
    if (e >= E) return;
    int s = clampi(ei[e], 0, NN - 1);
    int d = clampi(ei[E + e], 0, NN - 1);
    int pos = atomicAdd(&g_cursor[d], 1);
    pos = clampi(pos, 0, NE - 1);
    g_csrc[pos]  = s;
    g_cnorm[pos] = g_dis[s] * g_dis[d];
}

// ---------------------------------------------------------------------------
// Tiled fp32 GEMM: g_h[n,64] = in[n,K] @ W[K,64]   (optional relu on load)
// Block: 256 threads -> 64-node x 64-out tile, 4x4 register micro-tile/thread
// ---------------------------------------------------------------------------
template <int K, bool RELU, bool FROM_GOUT>
__global__ __launch_bounds__(256)
void k_gemm64(const float* __restrict__ in_ptr, const float* __restrict__ W, int n) {
    const float* __restrict__ in = FROM_GOUT ? (const float*)g_out : in_ptr;

    __shared__ __align__(16) float Xs[64][33];   // [node][k]   (+pad)
    __shared__ __align__(16) float Ws[32][64];   // [k][out]

    const int tid = threadIdx.x;
    const int tx  = tid & 15;      // output group: outs tx*4 .. tx*4+3
    const int ty  = tid >> 4;      // node group:  nodes ty*4 .. ty*4+3
    const int nb  = blockIdx.x * 64;

    float acc[4][4];
#pragma unroll
    for (int i = 0; i < 4; i++)
#pragma unroll
        for (int j = 0; j < 4; j++) acc[i][j] = 0.0f;

    for (int kt = 0; kt < K; kt += 32) {
        // Load X tile (64 nodes x 32 k), coalesced, zero-fill OOB
        {
            const int k  = tid & 31;
            const int r0 = tid >> 5;      // 0..7
#pragma unroll
            for (int r = 0; r < 8; r++) {
                int node = r0 * 8 + r;
                int gn = nb + node;
                float v = 0.0f;
                if (gn < n) v = in[(size_t)gn * K + kt + k];
                if (RELU) v = fmaxf(v, 0.0f);
                Xs[node][k] = v;
            }
        }
        // Load W tile (32 k x 64 out), coalesced
        {
#pragma unroll
            for (int i = 0; i < 8; i++) {
                int flat = tid + i * 256;
                int wk = flat >> 6;
                int wo = flat & 63;
                Ws[wk][wo] = W[(size_t)(kt + wk) * 64 + wo];
            }
        }
        __syncthreads();

#pragma unroll
        for (int kk = 0; kk < 32; kk++) {
            float4 w = *(const float4*)&Ws[kk][tx * 4];
            float x0 = Xs[ty * 4 + 0][kk];
            float x1 = Xs[ty * 4 + 1][kk];
            float x2 = Xs[ty * 4 + 2][kk];
            float x3 = Xs[ty * 4 + 3][kk];
            acc[0][0] += x0 * w.x; acc[0][1] += x0 * w.y; acc[0][2] += x0 * w.z; acc[0][3] += x0 * w.w;
            acc[1][0] += x1 * w.x; acc[1][1] += x1 * w.y; acc[1][2] += x1 * w.z; acc[1][3] += x1 * w.w;
            acc[2][0] += x2 * w.x; acc[2][1] += x2 * w.y; acc[2][2] += x2 * w.z; acc[2][3] += x2 * w.w;
            acc[3][0] += x3 * w.x; acc[3][1] += x3 * w.y; acc[3][2] += x3 * w.z; acc[3][3] += x3 * w.w;
        }
        __syncthreads();
    }

#pragma unroll
    for (int i = 0; i < 4; i++) {
        int gn = nb + ty * 4 + i;
        if (gn < n) {
            float4 v = make_float4(acc[i][0], acc[i][1], acc[i][2], acc[i][3]);
            *(float4*)&g_h[(size_t)gn * 64 + tx * 4] = v;
        }
    }
}

// ---------------------------------------------------------------------------
// Atomic-free aggregation (gather over CSR-by-dst), fused self-loop + bias:
//   out[i,:] = h[i,:]*dis2[i] + b + sum_{e: dst=i} h[src_e,:]*norm_e
// Half-warp (16 threads, 4 floats each) per node.
// ---------------------------------------------------------------------------
__global__ __launch_bounds__(256)
void k_aggregate(const float* __restrict__ b, int n) {
    int t = blockIdx.x * blockDim.x + threadIdx.x;
    int node = t >> 4;
    if (node >= n) return;
    int c = (t & 15) * 4;

    float d2 = g_dis2[node];
    float4 h  = *(const float4*)&g_h[(size_t)node * 64 + c];
    float4 bb = *(const float4*)&b[c];
    float ax = h.x * d2 + bb.x;
    float ay = h.y * d2 + bb.y;
    float az = h.z * d2 + bb.z;
    float aw = h.w * d2 + bb.w;

    const int beg = g_start[node];
    const int cnt = g_indeg[node];

    int j = 0;
    // 2-way unrolled gather for memory-level parallelism
    for (; j + 2 <= cnt; j += 2) {
        int   s0 = g_csrc[beg + j];
        int   s1 = g_csrc[beg + j + 1];
        float n0 = g_cnorm[beg + j];
        float n1 = g_cnorm[beg + j + 1];
        float4 h0 = *(const float4*)&g_h[(size_t)s0 * 64 + c];
        float4 h1 = *(const float4*)&g_h[(size_t)s1 * 64 + c];
        ax += h0.x * n0; ay += h0.y * n0; az += h0.z * n0; aw += h0.w * n0;
        ax += h1.x * n1; ay += h1.y * n1; az += h1.z * n1; aw += h1.w * n1;
    }
    if (j < cnt) {
        int   s0 = g_csrc[beg + j];
        float n0 = g_cnorm[beg + j];
        float4 h0 = *(const float4*)&g_h[(size_t)s0 * 64 + c];
        ax += h0.x * n0; ay += h0.y * n0; az += h0.z * n0; aw += h0.w * n0;
    }

    float4 o = make_float4(ax, ay, az, aw);
    *(float4*)&g_out[(size_t)node * 64 + c] = o;
}

// ---------------------------------------------------------------------------
// Global mean pool — ATOMIC-FREE. `batch` is sorted, so each graph's nodes are
// contiguous. One block per graph: binary-search [lo, hi), reduce, plain store.
// ReLU applied on load of layer-3 output.
// ---------------------------------------------------------------------------
__global__ __launch_bounds__(256)
void k_pool(const int* __restrict__ batch, int n) {
    __shared__ int s_lo, s_hi;
    __shared__ float red[256];

    const int g = blockIdx.x;
    if (threadIdx.x == 0) {
        int lo = 0, hi = n;
        while (lo < hi) { int m = (lo + hi) >> 1; if (batch[m] < g) lo = m + 1; else hi = m; }
        s_lo = lo;
        int lo2 = lo, hi2 = n;
        while (lo2 < hi2) { int m = (lo2 + hi2) >> 1; if (batch[m] < g + 1) lo2 = m + 1; else hi2 = m; }
        s_hi = lo2;
    }
    __syncthreads();
    const int lo = s_lo, hi = s_hi;

    const int c = threadIdx.x & 63;    // channel
    const int r = threadIdx.x >> 6;    // 0..3 node-stride lane

    float acc = 0.0f;
    for (int node = lo + r; node < hi; node += 4)
        acc += fmaxf(g_out[(size_t)node * 64 + c], 0.0f);

    red[threadIdx.x] = acc;
    __syncthreads();
    if (r == 0) {
        float s = red[c] + red[64 + c] + red[128 + c] + red[192 + c];
        g_pool[g * 64 + c] = s;
        if (c == 0) g_cnt[g] = (float)(hi - lo);
    }
}

// ---------------------------------------------------------------------------
// Head: g = pool/cnt ; relu(g@fW1+fb1) ; @fW2+fb2 ; log_softmax
// One block, 64 threads (one per graph)
// ---------------------------------------------------------------------------
__global__ __launch_bounds__(64)
void k_head(const float* __restrict__ fW1, const float* __restrict__ fb1,
            const float* __restrict__ fW2, const float* __restrict__ fb2,
            float* __restrict__ out) {
    __shared__ float sW1[HID * 32];   // 64x32
    __shared__ float sW2[32 * NC];    // 32x16
    __shared__ float sb1[32];
    __shared__ float sb2[NC];

    int tid = threadIdx.x;
    for (int i = tid; i < HID * 32; i += 64) sW1[i] = fW1[i];
    for (int i = tid; i < 32 * NC;  i += 64) sW2[i] = fW2[i];
    if (tid < 32) sb1[tid] = fb1[tid];
    if (tid < NC) sb2[tid] = fb2[tid];
    __syncthreads();

    int g = tid;
    float inv = 1.0f / fmaxf(g_cnt[g], 1.0f);

    float gv[HID];
#pragma unroll
    for (int k = 0; k < HID; k++) gv[k] = g_pool[g * 64 + k] * inv;

    float h1[32];
#pragma unroll
    for (int j = 0; j < 32; j++) {
        float s = sb1[j];
#pragma unroll
        for (int k = 0; k < HID; k++) s += gv[k] * sW1[k * 32 + j];
        h1[j] = fmaxf(s, 0.0f);
    }

    float lg[NC];
#pragma unroll
    for (int c = 0; c < NC; c++) {
        float s = sb2[c];
#pragma unroll
        for (int j = 0; j < 32; j++) s += h1[j] * sW2[j * NC + c];
        lg[c] = s;
    }

    float m = lg[0];
#pragma unroll
    for (int c = 1; c < NC; c++) m = fmaxf(m, lg[c]);
    float se = 0.0f;
#pragma unroll
    for (int c = 0; c < NC; c++) se += expf(lg[c] - m);
    float lse = m + logf(se);
#pragma unroll
    for (int c = 0; c < NC; c++) out[g * NC + c] = lg[c] - lse;
}

// ---------------------------------------------------------------------------
// Launcher (graph-capturable: kernel launches only, default stream)
// ---------------------------------------------------------------------------
extern "C" void kernel_launch(void* const* d_in, const int* in_sizes, int n_in,
                              void* d_out, int out_size) {
    const float* x     = (const float*)d_in[0];
    const int*   ei    = (const int*)d_in[1];    // int32 per harness dtype rules
    const int*   batch = (const int*)d_in[2];    // int32 per harness dtype rules
    const float* W1  = (const float*)d_in[3];
    const float* b1  = (const float*)d_in[4];
    const float* W2  = (const float*)d_in[5];
    const float* b2  = (const float*)d_in[6];
    const float* W3  = (const float*)d_in[7];
    const float* b3  = (const float*)d_in[8];
    const float* fW1 = (const float*)d_in[9];
    const float* fb1 = (const float*)d_in[10];
    const float* fW2 = (const float*)d_in[11];
    const float* fb2 = (const float*)d_in[12];
    float* out = (float*)d_out;

    const int n = NN;
    const int E = NE;

    const int nb256  = (n + 255) / 256;
    const int eb256  = (E + 255) / 256;
    const int gemm_b = (n + 63) / 64;
    const int n16_b  = (n * 16 + 255) / 256;

    // CSR-by-dst build + normalization
    k_init<<<nb256, 256>>>(n);
    k_count<<<eb256, 256>>>(ei, E);
    k_offsets<<<nb256, 256>>>(n);
    k_place<<<eb256, 256>>>(ei, E);

    // Layer 1 (K=128, input x, no relu on load)
    k_gemm64<128, false, false><<<gemm_b, 256>>>(x, W1, n);
    k_aggregate<<<n16_b, 256>>>(b1, n);

    // Layer 2 (K=64, input relu(g_out))
    k_gemm64<64, true, true><<<gemm_b, 256>>>(nullptr, W2, n);
    k_aggregate<<<n16_b, 256>>>(b2, n);

    // Layer 3
    k_gemm64<64, true, true><<<gemm_b, 256>>>(nullptr, W3, n);
    k_aggregate<<<n16_b, 256>>>(b3, n);

    // Pool + head (all atomic-free in FP)
    k_pool<<<NG, 256>>>(batch, n);
    k_head<<<1, 64>>>(fW1, fb1, fW2, fb2, out);
}